// round 14
// baseline (speedup 1.0000x reference)
#include <cuda_runtime.h>
#include <cuda_fp16.h>
#include <cstdint>

// AWQ INT4 dequant GEMM: C[64,28672] = A[64,8192] @ deq(qweight) + bias
// f32 in (harness has no fp16), f32 out. mma.sync m16n8k16.
//
// R14: N-reuse doubled. 128 threads = 2 K-groups x 2 N-warps; each warp
// covers 32 N cols (nb=4), halving global A-fragment LDG traffic (the R13
// L1 wavefront wall). A read as per-thread fragments via coalesced LDG.128
// (prepass-tiled, L1/L2-cached, 1MB). q: 8 coalesced LDG.32/chunk + shfl
// redistribution. PRMT + vector-constant dequant (bitwise-exact reference
// fp16 weights). Static-smem two-pass split-K reduction epilogue.

#define MDIM 64
#define KDIM 8192
#define NDIM 28672
#define NGROUPS 64
#define NTILE 64
#define CHALF 64              // chunks per K-group
#define THREADS 128

__device__ __align__(16) uint4 g_Af[128 * 512];   // 1 MB: [chunk][s*4+mf][lane]

// Prepass: f32 A -> fp16 fragments.
// For (c, s, mf, lane): gidq=lane>>2, tj=lane&3, r0=mf*16+gidq, k0=c*64+s*16+2tj
//   x={A[r0][k0],A[r0][k0+1]} y={A[r0+8][k0],..} z={A[r0][k0+8],..} w={A[r0+8][k0+8],..}
__global__ void convert_A_frag(const float* __restrict__ A)
{
    int t = blockIdx.x * blockDim.x + threadIdx.x;
    if (t >= 128 * 512) return;
    const int c    = t >> 9;
    const int rest = t & 511;
    const int s    = rest >> 7;
    const int mf   = (rest >> 5) & 3;
    const int lane = rest & 31;
    const int gidq = lane >> 2;
    const int tj   = lane & 3;
    const int r0 = mf * 16 + gidq;
    const int k0 = c * 64 + s * 16 + 2 * tj;

    const float2 p0 = *reinterpret_cast<const float2*>(A + (size_t)r0 * KDIM + k0);
    const float2 p1 = *reinterpret_cast<const float2*>(A + (size_t)(r0 + 8) * KDIM + k0);
    const float2 p2 = *reinterpret_cast<const float2*>(A + (size_t)r0 * KDIM + k0 + 8);
    const float2 p3 = *reinterpret_cast<const float2*>(A + (size_t)(r0 + 8) * KDIM + k0 + 8);
    half2 h0 = __floats2half2_rn(p0.x, p0.y);
    half2 h1 = __floats2half2_rn(p1.x, p1.y);
    half2 h2 = __floats2half2_rn(p2.x, p2.y);
    half2 h3 = __floats2half2_rn(p3.x, p3.y);
    uint4 u;
    u.x = reinterpret_cast<uint32_t&>(h0);
    u.y = reinterpret_cast<uint32_t&>(h1);
    u.z = reinterpret_cast<uint32_t&>(h2);
    u.w = reinterpret_cast<uint32_t&>(h3);
    g_Af[t] = u;
}

__global__ __launch_bounds__(THREADS, 4)
void awq_gemm_kernel(const int*   __restrict__ qw,
                     const float* __restrict__ scales,
                     const float* __restrict__ bias,
                     float*       __restrict__ out)
{
    __shared__ float red[2048];   // 8 KB reduction buffer (two passes)

    const int tid  = threadIdx.x;
    const int lane = tid & 31;
    const int wid  = tid >> 5;
    const int rg   = wid >> 1;          // K-group 0/1 (warps {0,1} / {2,3})
    const int wn   = wid & 1;           // N-warp: cols [wn*32, wn*32+32)
    const int gidq = lane >> 2;         // 0..7
    const int tj   = lane & 3;          // 0..3
    const int n0   = blockIdx.x * NTILE;
    const int cb   = rg * CHALF;        // global chunk base

    const uint32_t selr = (uint32_t)tj * 0x1111u;   // PRMT: byte tj -> all bytes

    // q: word-row r (k rows 8r..8r+7 of chunk), col = lane within warp's 32.
    const int qcol = n0 + wn * 32 + lane;
    uint32_t qc[8], qn[8];
    #pragma unroll
    for (int r = 0; r < 8; ++r)
        qc[r] = __ldg((const uint32_t*)qw + (size_t)(cb * 8 + r) * NDIM + qcol);

    // scales: cols n0 + wn*32 + nb*8 + gidq
    const int scol = n0 + wn * 32 + gidq;
    float sf[4];
    #pragma unroll
    for (int nb = 0; nb < 4; ++nb)
        sf[nb] = __ldg(scales + (size_t)(rg * 32) * NDIM + scol + nb * 8);

    float acc[4][4][4];                 // [mf][nb][frag]
    #pragma unroll
    for (int i = 0; i < 4; i++)
        #pragma unroll
        for (int j = 0; j < 4; j++)
            #pragma unroll
            for (int k = 0; k < 4; k++) acc[i][j][k] = 0.f;

    const uint32_t C2 = 0x64806408u;    // half2(1032.0, 1152.0)
    uint32_t sv[4];                     // per-nb vector scale {s, s/16}

    for (int c = 0; c < CHALF; ++c) {
        const int cg = cb + c;
        // q prefetch next chunk (8 coalesced LDG.32)
        if (c + 1 < CHALF) {
            #pragma unroll
            for (int r = 0; r < 8; ++r)
                qn[r] = __ldg((const uint32_t*)qw + (size_t)((cg + 1) * 8 + r) * NDIM + qcol);
        }
        // group scales (128 K = 2 chunks): {s, s/16} vectors (exact)
        if ((c & 1) == 0) {
            #pragma unroll
            for (int nb = 0; nb < 4; ++nb) {
                uint32_t b = (uint32_t)__half_as_ushort(__float2half_rn(sf[nb]));
                sv[nb] = b | ((b - 0x1000u) << 16);
            }
            const int gn = rg * 32 + (c >> 1) + 1;
            if (gn < (rg + 1) * 32) {
                #pragma unroll
                for (int nb = 0; nb < 4; ++nb)
                    sf[nb] = __ldg(scales + (size_t)gn * NDIM + scol + nb * 8);
            }
        }

        const uint4* afrag = g_Af + (size_t)cg * 512 + lane;

        #pragma unroll
        for (int s = 0; s < 4; ++s) {
            uint4 a[4];
            #pragma unroll
            for (int mf = 0; mf < 4; ++mf)
                a[mf] = __ldg(afrag + (s * 4 + mf) * 32);

            #pragma unroll
            for (int nb = 0; nb < 4; ++nb) {
                const int src = nb * 8 + gidq;
                uint32_t w0 = __shfl_sync(0xffffffffu, qc[2 * s],     src);
                uint32_t w1 = __shfl_sync(0xffffffffu, qc[2 * s + 1], src);
                uint32_t t0, t1;
                asm("prmt.b32 %0, %1, 0, %2;" : "=r"(t0) : "r"(w0), "r"(selr));
                asm("prmt.b32 %0, %1, 0, %2;" : "=r"(t1) : "r"(w1), "r"(selr));
                uint32_t v0 = (t0 & 0x00F0000Fu) | 0x64006400u;  // {1024+nlo, 1024+16*nhi}
                uint32_t v1 = (t1 & 0x00F0000Fu) | 0x64006400u;
                half2 h0 = __hmul2(__hsub2(reinterpret_cast<half2&>(v0),
                                           reinterpret_cast<const half2&>(C2)),
                                   reinterpret_cast<half2&>(sv[nb]));
                half2 h1 = __hmul2(__hsub2(reinterpret_cast<half2&>(v1),
                                           reinterpret_cast<const half2&>(C2)),
                                   reinterpret_cast<half2&>(sv[nb]));
                uint32_t b0 = reinterpret_cast<uint32_t&>(h0);
                uint32_t b1 = reinterpret_cast<uint32_t&>(h1);
                #pragma unroll
                for (int mf = 0; mf < 4; ++mf) {
                    asm volatile(
                        "mma.sync.aligned.m16n8k16.row.col.f32.f16.f16.f32 "
                        "{%0,%1,%2,%3}, {%4,%5,%6,%7}, {%8,%9}, {%0,%1,%2,%3};\n"
                        : "+f"(acc[mf][nb][0]), "+f"(acc[mf][nb][1]),
                          "+f"(acc[mf][nb][2]), "+f"(acc[mf][nb][3])
                        : "r"(a[mf].x), "r"(a[mf].y), "r"(a[mf].z), "r"(a[mf].w),
                          "r"(b0), "r"(b1));
                }
            }
        }
        #pragma unroll
        for (int r = 0; r < 8; ++r) qc[r] = qn[r];
    }

    // ---- intra-CTA split-K reduction + store (two passes, static smem) ----
    __syncthreads();
    #pragma unroll
    for (int half = 0; half < 2; ++half) {
        if (rg == 1) {
            float* dst = red + (wn * 32 + lane) * 32;
            #pragma unroll
            for (int mf2 = 0; mf2 < 2; ++mf2)
                #pragma unroll
                for (int nb = 0; nb < 4; ++nb)
                    #pragma unroll
                    for (int k = 0; k < 4; ++k)
                        dst[mf2 * 16 + nb * 4 + k] = acc[half * 2 + mf2][nb][k];
        }
        __syncthreads();
        if (rg == 0) {
            const float* src = red + (wn * 32 + lane) * 32;
            #pragma unroll
            for (int mf2 = 0; mf2 < 2; ++mf2) {
                const int mf = half * 2 + mf2;
                #pragma unroll
                for (int nb = 0; nb < 4; ++nb) {
                    float r0 = acc[mf][nb][0] + src[mf2 * 16 + nb * 4 + 0];
                    float r1 = acc[mf][nb][1] + src[mf2 * 16 + nb * 4 + 1];
                    float r2 = acc[mf][nb][2] + src[mf2 * 16 + nb * 4 + 2];
                    float r3 = acc[mf][nb][3] + src[mf2 * 16 + nb * 4 + 3];
                    const int col  = n0 + wn * 32 + nb * 8 + 2 * tj;
                    const int row0 = mf * 16 + gidq;
                    const float2 bf = *reinterpret_cast<const float2*>(bias + col);
                    half2 hb = __floats2half2_rn(bf.x, bf.y);
                    half2 o0 = __hadd2(__floats2half2_rn(r0, r1), hb);
                    half2 o1 = __hadd2(__floats2half2_rn(r2, r3), hb);
                    *reinterpret_cast<float2*>(out + (size_t)row0 * NDIM + col) =
                        make_float2(__low2float(o0), __high2float(o0));
                    *reinterpret_cast<float2*>(out + (size_t)(row0 + 8) * NDIM + col) =
                        make_float2(__low2float(o1), __high2float(o1));
                }
            }
        }
        __syncthreads();
    }
}

extern "C" void kernel_launch(void* const* d_in, const int* in_sizes, int n_in,
                              void* d_out, int out_size) {
    const float* A      = nullptr;
    const int*   qwt    = nullptr;
    const float* scales = nullptr;
    const float* bias   = nullptr;
    for (int i = 0; i < n_in; ++i) {
        switch (in_sizes[i]) {
            case MDIM * KDIM:        A      = (const float*)d_in[i]; break;
            case (KDIM / 8) * NDIM:  qwt    = (const int*)d_in[i];   break;
            case NGROUPS * NDIM:     scales = (const float*)d_in[i]; break;
            case NDIM:               bias   = (const float*)d_in[i]; break;
            default: break;
        }
    }
    float* out = (float*)d_out;

    convert_A_frag<<<256, 256>>>(A);
    awq_gemm_kernel<<<NDIM / NTILE, THREADS>>>(qwt, scales, bias, out);  // 448 CTAs
}

// round 16
// speedup vs baseline: 1.3946x; 1.3946x over previous
#include <cuda_runtime.h>
#include <cuda_fp16.h>
#include <cstdint>

// AWQ INT4 dequant GEMM: C[64,28672] = A[64,8192] @ deq(qweight) + bias
// f32 in (harness has no fp16), f32 out. mma.sync m16n8k16.
//
// R15 = R13 (118.8us, proven) with the q path reworked: per-warp 3-stage
// cp.async ring (1 x 16B cp.async per lane per chunk) + broadcast LDS reads
// replace the 8 LDG + 32 SHFL (26-cyc chains) per chunk. One __syncwarp per
// chunk; no cross-warp coupling. A fragments via coalesced LDG.128 from the
// prepass-tiled 1MB buffer. PRMT + vector-constant dequant (bitwise-exact
// reference fp16 weights). Intra-CTA split-K 2x4 warps; static-smem two-pass
// reduction epilogue (verified R12/R13).

#define MDIM 64
#define KDIM 8192
#define NDIM 28672
#define NGROUPS 64
#define NTILE 64
#define CHALF 64              // chunks per K-group
#define THREADS 256

__device__ __align__(16) uint4 g_Af[128 * 512];   // 1 MB: [chunk][s*4+mf][lane]

__device__ __forceinline__ uint32_t smem_u32(const void* p) {
    return (uint32_t)__cvta_generic_to_shared(p);
}

// Prepass: f32 A -> fp16 fragments.
// For (c, s, mf, lane): gidq=lane>>2, tj=lane&3, r0=mf*16+gidq, k0=c*64+s*16+2tj
//   x={A[r0][k0],A[r0][k0+1]} y={A[r0+8][k0],..} z={A[r0][k0+8],..} w={A[r0+8][k0+8],..}
__global__ void convert_A_frag(const float* __restrict__ A)
{
    int t = blockIdx.x * blockDim.x + threadIdx.x;
    if (t >= 128 * 512) return;
    const int c    = t >> 9;
    const int rest = t & 511;
    const int s    = rest >> 7;
    const int mf   = (rest >> 5) & 3;
    const int lane = rest & 31;
    const int gidq = lane >> 2;
    const int tj   = lane & 3;
    const int r0 = mf * 16 + gidq;
    const int k0 = c * 64 + s * 16 + 2 * tj;

    const float2 p0 = *reinterpret_cast<const float2*>(A + (size_t)r0 * KDIM + k0);
    const float2 p1 = *reinterpret_cast<const float2*>(A + (size_t)(r0 + 8) * KDIM + k0);
    const float2 p2 = *reinterpret_cast<const float2*>(A + (size_t)r0 * KDIM + k0 + 8);
    const float2 p3 = *reinterpret_cast<const float2*>(A + (size_t)(r0 + 8) * KDIM + k0 + 8);
    half2 h0 = __floats2half2_rn(p0.x, p0.y);
    half2 h1 = __floats2half2_rn(p1.x, p1.y);
    half2 h2 = __floats2half2_rn(p2.x, p2.y);
    half2 h3 = __floats2half2_rn(p3.x, p3.y);
    uint4 u;
    u.x = reinterpret_cast<uint32_t&>(h0);
    u.y = reinterpret_cast<uint32_t&>(h1);
    u.z = reinterpret_cast<uint32_t&>(h2);
    u.w = reinterpret_cast<uint32_t&>(h3);
    g_Af[t] = u;
}

__global__ __launch_bounds__(THREADS, 3)
void awq_gemm_kernel(const int*   __restrict__ qw,
                     const float* __restrict__ scales,
                     const float* __restrict__ bias,
                     float*       __restrict__ out)
{
    __shared__ float red[2048];             // 8 KB reduction buffer
    __shared__ uint32_t qring[3 * 8 * 128]; // 12 KB: 3 stages x 8 warps x 512B

    const int tid  = threadIdx.x;
    const int lane = tid & 31;
    const int wid  = tid >> 5;
    const int rg   = wid >> 2;          // K-group 0/1
    const int wn   = wid & 3;           // N-warp: cols [wn*16, wn*16+16)
    const int gidq = lane >> 2;         // 0..7
    const int tj   = lane & 3;          // 0..3
    const int n0   = blockIdx.x * NTILE;
    const int cb   = rg * CHALF;        // global chunk base

    const uint32_t selr = (uint32_t)tj * 0x1111u;   // PRMT: byte tj -> all bytes

    // q cp.async mapping: lane copies 16B: word-row qlw = lane>>2, cols qlc..qlc+3
    const int qlw = lane >> 2;
    const int qlc = (lane & 3) * 4;
    const int* qsrc_base = qw + (size_t)qlw * NDIM + n0 + wn * 16 + qlc;

    auto issue_q = [&](int c) {   // c = chunk index within this K-group
        const int st  = c % 3;
        const int* src = qsrc_base + (size_t)(cb + c) * 8 * NDIM;
        uint32_t dst = smem_u32(&qring[(st * 8 + wid) * 128 + qlw * 16 + qlc]);
        asm volatile("cp.async.cg.shared.global [%0], [%1], 16;\n" :: "r"(dst), "l"(src));
        asm volatile("cp.async.commit_group;\n" ::: "memory");
    };

    // Prologue: stage chunks 0,1
    issue_q(0);
    issue_q(1);

    // scales: cols n0 + wn*16 + gidq (+8)
    const int scol = n0 + wn * 16 + gidq;
    float sf0 = __ldg(scales + (size_t)(rg * 32) * NDIM + scol);
    float sf1 = __ldg(scales + (size_t)(rg * 32) * NDIM + scol + 8);

    float acc[4][2][4];
    #pragma unroll
    for (int i = 0; i < 4; i++)
        #pragma unroll
        for (int j = 0; j < 2; j++)
            #pragma unroll
            for (int k = 0; k < 4; k++) acc[i][j][k] = 0.f;

    const uint32_t C2 = 0x64806408u;    // half2(1032.0, 1152.0)
    uint32_t sv[2];

    for (int c = 0; c < CHALF; ++c) {
        // stage c+2; wait until chunk c's group is complete
        if (c + 2 < CHALF) {
            issue_q(c + 2);
            asm volatile("cp.async.wait_group 2;\n" ::: "memory");
        } else if (c + 1 < CHALF) {
            asm volatile("cp.async.wait_group 1;\n" ::: "memory");
        } else {
            asm volatile("cp.async.wait_group 0;\n" ::: "memory");
        }
        __syncwarp();   // all lanes' q data visible; prior-stage readers done

        // group scales (128 K = 2 chunks): {s, s/16} vectors (exact)
        if ((c & 1) == 0) {
            uint32_t b0 = (uint32_t)__half_as_ushort(__float2half_rn(sf0));
            uint32_t b1 = (uint32_t)__half_as_ushort(__float2half_rn(sf1));
            sv[0] = b0 | ((b0 - 0x1000u) << 16);
            sv[1] = b1 | ((b1 - 0x1000u) << 16);
            const int gn = rg * 32 + (c >> 1) + 1;
            if (gn < (rg + 1) * 32) {
                sf0 = __ldg(scales + (size_t)gn * NDIM + scol);
                sf1 = __ldg(scales + (size_t)gn * NDIM + scol + 8);
            }
        }

        const uint4* afrag = g_Af + (size_t)(cb + c) * 512 + lane;
        const uint32_t* qwarp = &qring[((c % 3) * 8 + wid) * 128];

        #pragma unroll
        for (int s = 0; s < 4; ++s) {
            uint4 a[4];
            #pragma unroll
            for (int mf = 0; mf < 4; ++mf)
                a[mf] = __ldg(afrag + (s * 4 + mf) * 32);

            #pragma unroll
            for (int nb = 0; nb < 2; ++nb) {
                // broadcast LDS: 4 tj-lanes share one address, 8 banks across gidq
                uint32_t w0 = qwarp[(2 * s)     * 16 + nb * 8 + gidq];
                uint32_t w1 = qwarp[(2 * s + 1) * 16 + nb * 8 + gidq];
                uint32_t t0, t1;
                asm("prmt.b32 %0, %1, 0, %2;" : "=r"(t0) : "r"(w0), "r"(selr));
                asm("prmt.b32 %0, %1, 0, %2;" : "=r"(t1) : "r"(w1), "r"(selr));
                uint32_t v0 = (t0 & 0x00F0000Fu) | 0x64006400u;  // {1024+nlo, 1024+16*nhi}
                uint32_t v1 = (t1 & 0x00F0000Fu) | 0x64006400u;
                half2 h0 = __hmul2(__hsub2(reinterpret_cast<half2&>(v0),
                                           reinterpret_cast<const half2&>(C2)),
                                   reinterpret_cast<half2&>(sv[nb]));
                half2 h1 = __hmul2(__hsub2(reinterpret_cast<half2&>(v1),
                                           reinterpret_cast<const half2&>(C2)),
                                   reinterpret_cast<half2&>(sv[nb]));
                uint32_t b0 = reinterpret_cast<uint32_t&>(h0);
                uint32_t b1 = reinterpret_cast<uint32_t&>(h1);
                #pragma unroll
                for (int mf = 0; mf < 4; ++mf) {
                    asm volatile(
                        "mma.sync.aligned.m16n8k16.row.col.f32.f16.f16.f32 "
                        "{%0,%1,%2,%3}, {%4,%5,%6,%7}, {%8,%9}, {%0,%1,%2,%3};\n"
                        : "+f"(acc[mf][nb][0]), "+f"(acc[mf][nb][1]),
                          "+f"(acc[mf][nb][2]), "+f"(acc[mf][nb][3])
                        : "r"(a[mf].x), "r"(a[mf].y), "r"(a[mf].z), "r"(a[mf].w),
                          "r"(b0), "r"(b1));
                }
            }
        }
    }

    // ---- intra-CTA split-K reduction + store (verified R12/R13 epilogue) ----
    __syncthreads();
    #pragma unroll
    for (int half = 0; half < 2; ++half) {
        if (rg == 1) {
            float* dst = red + (wn * 32 + lane) * 16;
            #pragma unroll
            for (int mf2 = 0; mf2 < 2; ++mf2)
                #pragma unroll
                for (int nb = 0; nb < 2; ++nb)
                    #pragma unroll
                    for (int k = 0; k < 4; ++k)
                        dst[mf2 * 8 + nb * 4 + k] = acc[half * 2 + mf2][nb][k];
        }
        __syncthreads();
        if (rg == 0) {
            const float* src = red + (wn * 32 + lane) * 16;
            #pragma unroll
            for (int mf2 = 0; mf2 < 2; ++mf2) {
                const int mf = half * 2 + mf2;
                #pragma unroll
                for (int nb = 0; nb < 2; ++nb) {
                    float r0 = acc[mf][nb][0] + src[mf2 * 8 + nb * 4 + 0];
                    float r1 = acc[mf][nb][1] + src[mf2 * 8 + nb * 4 + 1];
                    float r2 = acc[mf][nb][2] + src[mf2 * 8 + nb * 4 + 2];
                    float r3 = acc[mf][nb][3] + src[mf2 * 8 + nb * 4 + 3];
                    const int col  = n0 + wn * 16 + nb * 8 + 2 * tj;
                    const int row0 = mf * 16 + gidq;
                    const float2 bf = *reinterpret_cast<const float2*>(bias + col);
                    half2 hb = __floats2half2_rn(bf.x, bf.y);
                    half2 o0 = __hadd2(__floats2half2_rn(r0, r1), hb);
                    half2 o1 = __hadd2(__floats2half2_rn(r2, r3), hb);
                    *reinterpret_cast<float2*>(out + (size_t)row0 * NDIM + col) =
                        make_float2(__low2float(o0), __high2float(o0));
                    *reinterpret_cast<float2*>(out + (size_t)(row0 + 8) * NDIM + col) =
                        make_float2(__low2float(o1), __high2float(o1));
                }
            }
        }
        __syncthreads();
    }
}

extern "C" void kernel_launch(void* const* d_in, const int* in_sizes, int n_in,
                              void* d_out, int out_size) {
    const float* A      = nullptr;
    const int*   qwt    = nullptr;
    const float* scales = nullptr;
    const float* bias   = nullptr;
    for (int i = 0; i < n_in; ++i) {
        switch (in_sizes[i]) {
            case MDIM * KDIM:        A      = (const float*)d_in[i]; break;
            case (KDIM / 8) * NDIM:  qwt    = (const int*)d_in[i];   break;
            case NGROUPS * NDIM:     scales = (const float*)d_in[i]; break;
            case NDIM:               bias   = (const float*)d_in[i]; break;
            default: break;
        }
    }
    float* out = (float*)d_out;

    convert_A_frag<<<256, 256>>>(A);
    awq_gemm_kernel<<<NDIM / NTILE, THREADS>>>(qwt, scales, bias, out);  // 448 CTAs
}

// round 17
// speedup vs baseline: 1.7019x; 1.2203x over previous
#include <cuda_runtime.h>
#include <cuda_fp16.h>
#include <cstdint>

// AWQ INT4 dequant GEMM: C[64,28672] = A[64,8192] @ deq(qweight) + bias
// f32 in (harness has no fp16), f32 out. mma.sync m16n8k16.
//
// R16 = R15 with the A path latency-hidden: per-K-group 3-stage cp.async
// ring in dynamic smem (fragment layout, cooperative fill: 4 x 16B cp.async
// per lane per chunk), consumed via guaranteed-hit LDS.128 instead of LDG
// that was missing L1 to L2 (234-262cy long-scoreboard stalls = the measured
// issue collapse). Named barrier per K-group per chunk (bar.sync rg+1,128);
// cp.async issued after the barrier so ring-stage reuse is race-free.
// q ring + broadcast LDS (R15), PRMT + vector-constant dequant (bit-exact),
// intra-CTA split-K 2x4 warps, static-smem two-pass reduction epilogue.

#define MDIM 64
#define KDIM 8192
#define NDIM 28672
#define NGROUPS 64
#define NTILE 64
#define CHALF 64              // chunks per K-group
#define THREADS 256
#define STAGES 3
#define A_STAGE_BYTES 8192    // 16 frags x 512 B
#define DSMEM (2 * STAGES * A_STAGE_BYTES)   // 48 KB dynamic (A rings)

__device__ __align__(16) uint4 g_Af[128 * 512];   // 1 MB: [chunk][s*4+mf][lane]

__device__ __forceinline__ uint32_t smem_u32(const void* p) {
    return (uint32_t)__cvta_generic_to_shared(p);
}

// Prepass: f32 A -> fp16 fragments.
// For (c, s, mf, lane): gidq=lane>>2, tj=lane&3, r0=mf*16+gidq, k0=c*64+s*16+2tj
//   x={A[r0][k0],A[r0][k0+1]} y={A[r0+8][k0],..} z={A[r0][k0+8],..} w={A[r0+8][k0+8],..}
__global__ void convert_A_frag(const float* __restrict__ A)
{
    int t = blockIdx.x * blockDim.x + threadIdx.x;
    if (t >= 128 * 512) return;
    const int c    = t >> 9;
    const int rest = t & 511;
    const int s    = rest >> 7;
    const int mf   = (rest >> 5) & 3;
    const int lane = rest & 31;
    const int gidq = lane >> 2;
    const int tj   = lane & 3;
    const int r0 = mf * 16 + gidq;
    const int k0 = c * 64 + s * 16 + 2 * tj;

    const float2 p0 = *reinterpret_cast<const float2*>(A + (size_t)r0 * KDIM + k0);
    const float2 p1 = *reinterpret_cast<const float2*>(A + (size_t)(r0 + 8) * KDIM + k0);
    const float2 p2 = *reinterpret_cast<const float2*>(A + (size_t)r0 * KDIM + k0 + 8);
    const float2 p3 = *reinterpret_cast<const float2*>(A + (size_t)(r0 + 8) * KDIM + k0 + 8);
    half2 h0 = __floats2half2_rn(p0.x, p0.y);
    half2 h1 = __floats2half2_rn(p1.x, p1.y);
    half2 h2 = __floats2half2_rn(p2.x, p2.y);
    half2 h3 = __floats2half2_rn(p3.x, p3.y);
    uint4 u;
    u.x = reinterpret_cast<uint32_t&>(h0);
    u.y = reinterpret_cast<uint32_t&>(h1);
    u.z = reinterpret_cast<uint32_t&>(h2);
    u.w = reinterpret_cast<uint32_t&>(h3);
    g_Af[t] = u;
}

__global__ __launch_bounds__(THREADS, 3)
void awq_gemm_kernel(const int*   __restrict__ qw,
                     const float* __restrict__ scales,
                     const float* __restrict__ bias,
                     float*       __restrict__ out)
{
    extern __shared__ __align__(16) char dynsm[];   // A rings, 48 KB
    __shared__ float red[2048];                     // 8 KB reduction buffer
    __shared__ uint32_t qring[3 * 8 * 128];         // 12 KB q ring

    const int tid  = threadIdx.x;
    const int lane = tid & 31;
    const int wid  = tid >> 5;
    const int rg   = wid >> 2;          // K-group 0/1
    const int wn   = wid & 3;           // N-warp: cols [wn*16, wn*16+16)
    const int gidq = lane >> 2;         // 0..7
    const int tj   = lane & 3;          // 0..3
    const int n0   = blockIdx.x * NTILE;
    const int cb   = rg * CHALF;        // global chunk base

    const uint32_t selr = (uint32_t)tj * 0x1111u;   // PRMT: byte tj -> all bytes

    const uint32_t Aring = smem_u32(dynsm) + (uint32_t)rg * (STAGES * A_STAGE_BYTES);

    // A fill mapping: warp wn copies frags [wn*4, wn*4+4), one 16B per lane per frag
    const uint4*  asrc_base = g_Af + (size_t)cb * 512 + (wn * 4) * 32 + lane;
    const uint32_t adst_base = Aring + (uint32_t)(wn * 4) * 512 + lane * 16;

    // q cp.async mapping (R15): lane copies 16B: word-row qlw, cols qlc..qlc+3
    const int qlw = lane >> 2;
    const int qlc = (lane & 3) * 4;
    const int* qsrc_base = qw + (size_t)qlw * NDIM + n0 + wn * 16 + qlc;

    auto issue_chunk = [&](int c) {   // c = chunk index within this K-group
        const int st = c % STAGES;
        const uint4* asrc = asrc_base + (size_t)c * 512;
        uint32_t adst = adst_base + st * A_STAGE_BYTES;
        #pragma unroll
        for (int f = 0; f < 4; ++f)
            asm volatile("cp.async.cg.shared.global [%0], [%1], 16;\n"
                         :: "r"(adst + f * 512), "l"(asrc + f * 32));
        const int* src = qsrc_base + (size_t)(cb + c) * 8 * NDIM;
        uint32_t dst = smem_u32(&qring[(st * 8 + wid) * 128 + qlw * 16 + qlc]);
        asm volatile("cp.async.cg.shared.global [%0], [%1], 16;\n" :: "r"(dst), "l"(src));
        asm volatile("cp.async.commit_group;\n" ::: "memory");
    };

    // Prologue: stage chunks 0,1
    issue_chunk(0);
    issue_chunk(1);

    // scales: cols n0 + wn*16 + gidq (+8)
    const int scol = n0 + wn * 16 + gidq;
    float sf0 = __ldg(scales + (size_t)(rg * 32) * NDIM + scol);
    float sf1 = __ldg(scales + (size_t)(rg * 32) * NDIM + scol + 8);

    float acc[4][2][4];
    #pragma unroll
    for (int i = 0; i < 4; i++)
        #pragma unroll
        for (int j = 0; j < 2; j++)
            #pragma unroll
            for (int k = 0; k < 4; k++) acc[i][j][k] = 0.f;

    const uint32_t C2 = 0x64806408u;    // half2(1032.0, 1152.0)
    uint32_t sv[2];
    const int barid = rg + 1;           // named barrier per K-group (id 1 / 2)

    for (int c = 0; c < CHALF; ++c) {
        // my chunk-c group complete (outstanding: {c, c+1} -> wait 1; tail -> 0)
        if (c + 1 < CHALF) {
            asm volatile("cp.async.wait_group 1;\n" ::: "memory");
        } else {
            asm volatile("cp.async.wait_group 0;\n" ::: "memory");
        }
        // all 4 warps of this K-group landed their pieces; also fences stage reuse
        asm volatile("bar.sync %0, 128;" :: "r"(barid) : "memory");
        if (c + 2 < CHALF) issue_chunk(c + 2);

        // group scales (128 K = 2 chunks): {s, s/16} vectors (exact)
        if ((c & 1) == 0) {
            uint32_t b0 = (uint32_t)__half_as_ushort(__float2half_rn(sf0));
            uint32_t b1 = (uint32_t)__half_as_ushort(__float2half_rn(sf1));
            sv[0] = b0 | ((b0 - 0x1000u) << 16);
            sv[1] = b1 | ((b1 - 0x1000u) << 16);
            const int gn = rg * 32 + (c >> 1) + 1;
            if (gn < (rg + 1) * 32) {
                sf0 = __ldg(scales + (size_t)gn * NDIM + scol);
                sf1 = __ldg(scales + (size_t)gn * NDIM + scol + 8);
            }
        }

        const uint32_t ast = Aring + (c % STAGES) * A_STAGE_BYTES + lane * 16;
        const uint32_t* qwarp = &qring[((c % STAGES) * 8 + wid) * 128];

        #pragma unroll
        for (int s = 0; s < 4; ++s) {
            uint4 a[4];
            #pragma unroll
            for (int mf = 0; mf < 4; ++mf)
                asm volatile("ld.shared.v4.b32 {%0,%1,%2,%3}, [%4];"
                             : "=r"(a[mf].x), "=r"(a[mf].y), "=r"(a[mf].z), "=r"(a[mf].w)
                             : "r"(ast + (s * 4 + mf) * 512));

            #pragma unroll
            for (int nb = 0; nb < 2; ++nb) {
                // broadcast LDS: 4 tj-lanes share one address, 8 banks across gidq
                uint32_t w0 = qwarp[(2 * s)     * 16 + nb * 8 + gidq];
                uint32_t w1 = qwarp[(2 * s + 1) * 16 + nb * 8 + gidq];
                uint32_t t0, t1;
                asm("prmt.b32 %0, %1, 0, %2;" : "=r"(t0) : "r"(w0), "r"(selr));
                asm("prmt.b32 %0, %1, 0, %2;" : "=r"(t1) : "r"(w1), "r"(selr));
                uint32_t v0 = (t0 & 0x00F0000Fu) | 0x64006400u;  // {1024+nlo, 1024+16*nhi}
                uint32_t v1 = (t1 & 0x00F0000Fu) | 0x64006400u;
                half2 h0 = __hmul2(__hsub2(reinterpret_cast<half2&>(v0),
                                           reinterpret_cast<const half2&>(C2)),
                                   reinterpret_cast<half2&>(sv[nb]));
                half2 h1 = __hmul2(__hsub2(reinterpret_cast<half2&>(v1),
                                           reinterpret_cast<const half2&>(C2)),
                                   reinterpret_cast<half2&>(sv[nb]));
                uint32_t b0 = reinterpret_cast<uint32_t&>(h0);
                uint32_t b1 = reinterpret_cast<uint32_t&>(h1);
                #pragma unroll
                for (int mf = 0; mf < 4; ++mf) {
                    asm volatile(
                        "mma.sync.aligned.m16n8k16.row.col.f32.f16.f16.f32 "
                        "{%0,%1,%2,%3}, {%4,%5,%6,%7}, {%8,%9}, {%0,%1,%2,%3};\n"
                        : "+f"(acc[mf][nb][0]), "+f"(acc[mf][nb][1]),
                          "+f"(acc[mf][nb][2]), "+f"(acc[mf][nb][3])
                        : "r"(a[mf].x), "r"(a[mf].y), "r"(a[mf].z), "r"(a[mf].w),
                          "r"(b0), "r"(b1));
                }
            }
        }
    }

    // ---- intra-CTA split-K reduction + store (verified epilogue) ----
    __syncthreads();
    #pragma unroll
    for (int half = 0; half < 2; ++half) {
        if (rg == 1) {
            float* dst = red + (wn * 32 + lane) * 16;
            #pragma unroll
            for (int mf2 = 0; mf2 < 2; ++mf2)
                #pragma unroll
                for (int nb = 0; nb < 2; ++nb)
                    #pragma unroll
                    for (int k = 0; k < 4; ++k)
                        dst[mf2 * 8 + nb * 4 + k] = acc[half * 2 + mf2][nb][k];
        }
        __syncthreads();
        if (rg == 0) {
            const float* src = red + (wn * 32 + lane) * 16;
            #pragma unroll
            for (int mf2 = 0; mf2 < 2; ++mf2) {
                const int mf = half * 2 + mf2;
                #pragma unroll
                for (int nb = 0; nb < 2; ++nb) {
                    float r0 = acc[mf][nb][0] + src[mf2 * 8 + nb * 4 + 0];
                    float r1 = acc[mf][nb][1] + src[mf2 * 8 + nb * 4 + 1];
                    float r2 = acc[mf][nb][2] + src[mf2 * 8 + nb * 4 + 2];
                    float r3 = acc[mf][nb][3] + src[mf2 * 8 + nb * 4 + 3];
                    const int col  = n0 + wn * 16 + nb * 8 + 2 * tj;
                    const int row0 = mf * 16 + gidq;
                    const float2 bf = *reinterpret_cast<const float2*>(bias + col);
                    half2 hb = __floats2half2_rn(bf.x, bf.y);
                    half2 o0 = __hadd2(__floats2half2_rn(r0, r1), hb);
                    half2 o1 = __hadd2(__floats2half2_rn(r2, r3), hb);
                    *reinterpret_cast<float2*>(out + (size_t)row0 * NDIM + col) =
                        make_float2(__low2float(o0), __high2float(o0));
                    *reinterpret_cast<float2*>(out + (size_t)(row0 + 8) * NDIM + col) =
                        make_float2(__low2float(o1), __high2float(o1));
                }
            }
        }
        __syncthreads();
    }
}

extern "C" void kernel_launch(void* const* d_in, const int* in_sizes, int n_in,
                              void* d_out, int out_size) {
    const float* A      = nullptr;
    const int*   qwt    = nullptr;
    const float* scales = nullptr;
    const float* bias   = nullptr;
    for (int i = 0; i < n_in; ++i) {
        switch (in_sizes[i]) {
            case MDIM * KDIM:        A      = (const float*)d_in[i]; break;
            case (KDIM / 8) * NDIM:  qwt    = (const int*)d_in[i];   break;
            case NGROUPS * NDIM:     scales = (const float*)d_in[i]; break;
            case NDIM:               bias   = (const float*)d_in[i]; break;
            default: break;
        }
    }
    float* out = (float*)d_out;

    cudaFuncSetAttribute(awq_gemm_kernel, cudaFuncAttributeMaxDynamicSharedMemorySize, DSMEM);
    convert_A_frag<<<256, 256>>>(A);
    awq_gemm_kernel<<<NDIM / NTILE, THREADS, DSMEM>>>(qwt, scales, bias, out);  // 448 CTAs
}